// round 3
// baseline (speedup 1.0000x reference)
#include <cuda_runtime.h>

#define POOL 7
#define FM_H 64
#define FM_W 64
#define FM_C 128          // channels, fp32
#define C_VEC (FM_C / 4)  // 32 float4 per pixel

__global__ __launch_bounds__(256, 8)
void roi_pool_kernel(const float4* __restrict__ fm4,
                     const int* __restrict__ rois,
                     float4* __restrict__ out4,
                     int n_rois)
{
    int roi = blockIdx.x;
    if (roi >= n_rois) return;

    const int rx1 = rois[roi * 4 + 0];
    const int ry1 = rois[roi * 4 + 1];
    const int rx2 = rois[roi * 4 + 2];
    const int ry2 = rois[roi * 4 + 3];

    const bool zero_roi = (rx1 == 0) & (ry1 == 0) & (rx2 == 0) & (ry2 == 0);

    __shared__ int   sy0[POOL], sy1[POOL], sx0[POOL], sx1[POOL];
    __shared__ float swy[POOL], swx[POOL];

    const int t = threadIdx.x;

    // Precompute sample coordinates exactly like the reference:
    // yc = clip((j+0.5)*hf/POOL - 0.5, 0, hf-1); y0=floor(yc); y1=min(y0+1,hh-1)
    if (t < POOL) {
        int hh = max(ry2 - ry1, 1);
        float hf = (float)hh;
        float yc = __fdiv_rn(((float)t + 0.5f) * hf, (float)POOL) - 0.5f;
        yc = fminf(fmaxf(yc, 0.0f), hf - 1.0f);
        int y0 = (int)floorf(yc);
        sy0[t] = y0 + ry1;
        sy1[t] = min(y0 + 1, hh - 1) + ry1;
        swy[t] = yc - (float)y0;
    } else if (t < 2 * POOL) {
        int j = t - POOL;
        int ww = max(rx2 - rx1, 1);
        float wf = (float)ww;
        float xc = __fdiv_rn(((float)j + 0.5f) * wf, (float)POOL) - 0.5f;
        xc = fminf(fmaxf(xc, 0.0f), wf - 1.0f);
        int x0 = (int)floorf(xc);
        sx0[j] = x0 + rx1;
        sx1[j] = min(x0 + 1, ww - 1) + rx1;
        swx[j] = xc - (float)x0;
    }
    __syncthreads();

    // Output base for this ROI: 49 positions * 32 float4 each
    float4* obase = out4 + (size_t)roi * (POOL * POOL * C_VEC);

    const int warp = t >> 5;
    const int lane = t & 31;

    for (int p = warp; p < POOL * POOL; p += 8) {
        float4* optr = obase + p * C_VEC + lane;

        if (zero_roi) {
            *optr = make_float4(0.0f, 0.0f, 0.0f, 0.0f);
            continue;
        }

        const int py = p / POOL;
        const int px = p - py * POOL;

        const int ya0 = sy0[py], ya1 = sy1[py];
        const int xa0 = sx0[px], xa1 = sx1[px];
        const float wy = swy[py], wx = swx[px];

        const float4 g00 = __ldg(fm4 + ((size_t)ya0 * FM_W + xa0) * C_VEC + lane);
        const float4 g01 = __ldg(fm4 + ((size_t)ya0 * FM_W + xa1) * C_VEC + lane);
        const float4 g10 = __ldg(fm4 + ((size_t)ya1 * FM_W + xa0) * C_VEC + lane);
        const float4 g11 = __ldg(fm4 + ((size_t)ya1 * FM_W + xa1) * C_VEC + lane);

        // top = g00 + wx*(g01-g00); bot = g10 + wx*(g11-g10); out = top + wy*(bot-top)
        float4 r;
        {
            float top = g00.x + wx * (g01.x - g00.x);
            float bot = g10.x + wx * (g11.x - g10.x);
            r.x = top + wy * (bot - top);
        }
        {
            float top = g00.y + wx * (g01.y - g00.y);
            float bot = g10.y + wx * (g11.y - g10.y);
            r.y = top + wy * (bot - top);
        }
        {
            float top = g00.z + wx * (g01.z - g00.z);
            float bot = g10.z + wx * (g11.z - g10.z);
            r.z = top + wy * (bot - top);
        }
        {
            float top = g00.w + wx * (g01.w - g00.w);
            float bot = g10.w + wx * (g11.w - g10.w);
            r.w = top + wy * (bot - top);
        }

        *optr = r;
    }
}

extern "C" void kernel_launch(void* const* d_in, const int* in_sizes, int n_in,
                              void* d_out, int out_size)
{
    const float4* fm4  = (const float4*)d_in[0];   // (1,64,64,128) fp32
    const int*    rois = (const int*)d_in[1];      // (1,N,4) int32
    float4*       out4 = (float4*)d_out;           // (1,N,7,7,128) fp32

    const int n_rois = in_sizes[1] / 4;

    roi_pool_kernel<<<n_rois, 256>>>(fm4, rois, out4, n_rois);
}